// round 10
// baseline (speedup 1.0000x reference)
#include <cuda_runtime.h>
#include <cuda_fp16.h>
#include <cstdint>
#include <math.h>

// TopK router: logits = X[16384,4096] @ W[64,4096]^T, top-2 + softmax.
// 3-term 2-level fp16 split on mma.sync.m16n8k16 (fp32 accum), split-K=2.
// W: pre-split + pre-swizzled + stage-blocked in gmem by prep_w; staged to
//    smem with ONE cp.async.bulk (16KB) per stage + mbarrier expect_tx.
// X: LDG.128 -> in-register fp16 split -> STS.128 (8 k per store) into
//    XOR-unit-swizzled smem; ldmatrix per-lane addressing matches.

#define DIM     4096
#define NEXP    64
#define MTILE   64
#define KC      64
#define KSPLIT  2
#define KHALF   (DIM / KSPLIT)      // 2048
#define NCH_H   (KHALF / KC)        // 32 stages per CTA
#define NCH_ALL (DIM / KC)          // 64 global stages
#define NTOK    16384
#define THREADS 256
#define INV2048 4.8828125e-4f

#define X0_OFF  0                   // 8KB  (64 rows x 128B)
#define X1_OFF  8192                // 8KB
#define W_OFF   16384               // 16KB (w0 8KB | w1 8KB)
#define STAGE_SZ 32768
#define MB_OFF  65536               // two mbarriers after the 2 stage buffers
#define SMEM_TOTAL (2 * STAGE_SZ + 64)
#define LROW 65

__device__ __align__(16) uint8_t g_wst[NCH_ALL * 16384];   // 1MB staged W
__device__ float g_part[KSPLIT * NTOK * NEXP];             // 8MB partials

// ---------- helpers ----------
__device__ __forceinline__ uint32_t smem_u32(const void* p) {
    uint32_t a;
    asm("{ .reg .u64 t; cvta.to.shared.u64 t, %1; cvt.u32.u64 %0, t; }" : "=r"(a) : "l"(p));
    return a;
}
__device__ __forceinline__ uint32_t swz(uint32_t o) { return o ^ ((o >> 3) & 0x70); }

__device__ __forceinline__ uint32_t pack_f16(float hi, float lo) {
    uint32_t r;
    asm("cvt.rn.f16x2.f32 %0, %1, %2;" : "=r"(r) : "f"(hi), "f"(lo));
    return r;
}
__device__ __forceinline__ float2 unpack_f16(uint32_t u) {
    __half2 h = *reinterpret_cast<__half2*>(&u);
    return __half22float2(h);
}
__device__ __forceinline__ void sts128(uint32_t a, uint32_t x, uint32_t y,
                                       uint32_t z, uint32_t w) {
    asm volatile("st.shared.v4.b32 [%0], {%1, %2, %3, %4};"
                 :: "r"(a), "r"(x), "r"(y), "r"(z), "r"(w) : "memory");
}
__device__ __forceinline__ void ldsm4(uint32_t r[4], uint32_t addr) {
    asm volatile("ldmatrix.sync.aligned.m8n8.x4.shared.b16 {%0,%1,%2,%3}, [%4];"
                 : "=r"(r[0]), "=r"(r[1]), "=r"(r[2]), "=r"(r[3]) : "r"(addr));
}
__device__ __forceinline__ void mma16816(float d[4], const uint32_t a[4],
                                         uint32_t b0, uint32_t b1) {
    asm volatile("mma.sync.aligned.m16n8k16.row.col.f32.f16.f16.f32 "
                 "{%0,%1,%2,%3}, {%4,%5,%6,%7}, {%8,%9}, {%0,%1,%2,%3};"
                 : "+f"(d[0]), "+f"(d[1]), "+f"(d[2]), "+f"(d[3])
                 : "r"(a[0]), "r"(a[1]), "r"(a[2]), "r"(a[3]), "r"(b0), "r"(b1));
}

#define MBARRIER_INIT(addr, cnt) \
    asm volatile("mbarrier.init.shared.b64 [%0], %1;" \
                 :: "r"((uint32_t)(addr)), "r"((uint32_t)(cnt)) : "memory")
#define MBARRIER_EXPECT_TX(addr, tx) \
    asm volatile("mbarrier.arrive.expect_tx.shared.b64 _, [%0], %1;" \
                 :: "r"((uint32_t)(addr)), "r"((uint32_t)(tx)) : "memory")
#define MBARRIER_WAIT_PARITY(mbar_smem_addr, phase_parity) do { \
    uint32_t _mbar = (uint32_t)(mbar_smem_addr); \
    uint32_t _parity = (uint32_t)(phase_parity); \
    uint32_t _done; \
    asm volatile("{\n\t.reg .pred p;\n\t" \
        "mbarrier.try_wait.parity.acquire.cta.shared::cta.b64 p, [%1], %2;\n\t" \
        "selp.b32 %0, 1, 0, p;\n\t}" \
        : "=r"(_done) : "r"(_mbar), "r"(_parity) : "memory"); \
    if (!_done) { \
        asm volatile("{\n\t.reg .pred P1;\n\t" \
            "WAIT_LOOP_%=:\n\t" \
            "mbarrier.try_wait.parity.acquire.cta.shared::cta.b64 P1, [%0], %1, 0x989680;\n\t" \
            "@P1 bra.uni WAIT_DONE_%=;\n\t" \
            "bra.uni WAIT_LOOP_%=;\n\t" \
            "WAIT_DONE_%=:\n\t}" \
            :: "r"(_mbar), "r"(_parity) : "memory"); \
    } \
} while (0)

__device__ __forceinline__ void bulk_g2s(uint32_t dst, const void* src,
                                         uint32_t bytes, uint32_t mbar) {
    asm volatile(
        "cp.async.bulk.shared::cta.global.mbarrier::complete_tx::bytes "
        "[%0], [%1], %2, [%3];"
        :: "r"(dst), "l"(src), "r"(bytes), "r"(mbar) : "memory");
}

// ---------- W prep: split + swizzle + stage-block ----------
__global__ void prep_w(const float* __restrict__ W) {
    const int uid = blockIdx.x * blockDim.x + threadIdx.x;  // 0..32767
    const int gs = uid >> 9;          // global stage 0..63
    const int r  = (uid >> 3) & 63;   // expert row
    const int c  = uid & 7;           // 8-k unit
    const float* src = W + (size_t)r * DIM + gs * KC + c * 8;
    float4 v0 = *(const float4*)src;
    float4 v1 = *(const float4*)(src + 4);

    uint32_t h0 = pack_f16(v0.y, v0.x), h1 = pack_f16(v0.w, v0.z);
    uint32_t h2 = pack_f16(v1.y, v1.x), h3 = pack_f16(v1.w, v1.z);
    float2 u0 = unpack_f16(h0), u1 = unpack_f16(h1);
    float2 u2 = unpack_f16(h2), u3 = unpack_f16(h3);
    uint32_t l0 = pack_f16((v0.y - u0.y) * 2048.0f, (v0.x - u0.x) * 2048.0f);
    uint32_t l1 = pack_f16((v0.w - u1.y) * 2048.0f, (v0.z - u1.x) * 2048.0f);
    uint32_t l2 = pack_f16((v1.y - u2.y) * 2048.0f, (v1.x - u2.x) * 2048.0f);
    uint32_t l3 = pack_f16((v1.w - u3.y) * 2048.0f, (v1.z - u3.x) * 2048.0f);

    uint8_t* base = g_wst + (size_t)gs * 16384;
    const uint32_t off = swz((uint32_t)(r * 128 + c * 16));
    *(uint4*)(base + off)        = make_uint4(h0, h1, h2, h3);
    *(uint4*)(base + 8192 + off) = make_uint4(l0, l1, l2, l3);
}

// ---------- X staging ----------
__device__ __forceinline__ void load_x(const float* __restrict__ xg0,
                                       const float* __restrict__ xg1,
                                       int s, float4 x[4]) {
    x[0] = *(const float4*)(xg0 + s * KC);
    x[1] = *(const float4*)(xg0 + s * KC + 4);
    x[2] = *(const float4*)(xg1 + s * KC);
    x[3] = *(const float4*)(xg1 + s * KC + 4);
}

__device__ __forceinline__ void store_x_unit(uint32_t tbase, int row, int k8,
                                             float4 v0, float4 v1) {
    uint32_t h0 = pack_f16(v0.y, v0.x), h1 = pack_f16(v0.w, v0.z);
    uint32_t h2 = pack_f16(v1.y, v1.x), h3 = pack_f16(v1.w, v1.z);
    float2 u0 = unpack_f16(h0), u1 = unpack_f16(h1);
    float2 u2 = unpack_f16(h2), u3 = unpack_f16(h3);
    uint32_t l0 = pack_f16((v0.y - u0.y) * 2048.0f, (v0.x - u0.x) * 2048.0f);
    uint32_t l1 = pack_f16((v0.w - u1.y) * 2048.0f, (v0.z - u1.x) * 2048.0f);
    uint32_t l2 = pack_f16((v1.y - u2.y) * 2048.0f, (v1.x - u2.x) * 2048.0f);
    uint32_t l3 = pack_f16((v1.w - u3.y) * 2048.0f, (v1.z - u3.x) * 2048.0f);
    const uint32_t off = (uint32_t)(row * 128 + (((k8) ^ (row & 7)) & 7) * 16);
    sts128(tbase + X0_OFF + off, h0, h1, h2, h3);
    sts128(tbase + X1_OFF + off, l0, l1, l2, l3);
}

// ---------- main kernel (partial GEMM over one K-half) ----------
__global__ void __launch_bounds__(THREADS, 3)
router_main(const float* __restrict__ X) {
    extern __shared__ __align__(1024) char smem[];
    const uint32_t sb = smem_u32(smem);
    const int tid  = threadIdx.x;
    const int lane = tid & 31;
    const int wid  = tid >> 5;
    const int m0   = blockIdx.x * MTILE;
    const int kh   = blockIdx.y;
    const int kbase = kh * KHALF;
    const int gs0   = kh * NCH_H;     // first global W stage

    // X loader: thread -> (row, k8) and (row+32, k8)
    const int xrow = tid >> 3;        // 0..31
    const int xk8  = tid & 7;
    const float* xg0 = X + (size_t)(m0 + xrow) * DIM + kbase + xk8 * 8;
    const float* xg1 = xg0 + (size_t)32 * DIM;

    // compute mapping
    const int slab = wid & 3;
    const int half = wid >> 2;
    const int t8   = lane & 7;
    const int mat  = lane >> 3;
    const int rsel = (mat & 1) * 8;
    const int kblk = mat >> 1;        // 0/1 : which k8 of the k16
    const int bsel = kblk * 16;
    const int arow = slab * 16 + t8 + rsel;   // token row for A lanes
    const int axor = arow & 7;

    const uint32_t mb0 = sb + MB_OFF;
    const uint32_t mb1 = sb + MB_OFF + 8;

    float acc0[4][4], acc1[4][4];
#pragma unroll
    for (int n = 0; n < 4; n++)
#pragma unroll
        for (int j = 0; j < 4; j++) { acc0[n][j] = 0.0f; acc1[n][j] = 0.0f; }

    if (tid == 0) { MBARRIER_INIT(mb0, 1); MBARRIER_INIT(mb1, 1); }
    __syncthreads();

    // prologue: W(0) bulk -> buf0; X(0) -> buf0; X(1) -> regs
    float4 xr[4];
    if (tid == 0) {
        MBARRIER_EXPECT_TX(mb0, 16384);
        bulk_g2s(sb + W_OFF, g_wst + (size_t)gs0 * 16384, 16384, mb0);
    }
    load_x(xg0, xg1, 0, xr);
    store_x_unit(sb, xrow, xk8, xr[0], xr[1]);
    store_x_unit(sb, xrow + 32, xk8, xr[2], xr[3]);
    load_x(xg0, xg1, 1, xr);
    __syncthreads();

    for (int s = 0; s < NCH_H; s++) {
        if (s + 1 < NCH_H) {
            const uint32_t nb = sb + ((s + 1) & 1) * STAGE_SZ;
            store_x_unit(nb, xrow, xk8, xr[0], xr[1]);
            store_x_unit(nb, xrow + 32, xk8, xr[2], xr[3]);
            if (tid == 0) {
                const uint32_t mbn = ((s + 1) & 1) ? mb1 : mb0;
                MBARRIER_EXPECT_TX(mbn, 16384);
                bulk_g2s(nb + W_OFF, g_wst + (size_t)(gs0 + s + 1) * 16384,
                         16384, mbn);
            }
        }
        if (s + 2 < NCH_H)
            load_x(xg0, xg1, s + 2, xr);

        // W(s) ready?
        MBARRIER_WAIT_PARITY((s & 1) ? mb1 : mb0, (s >> 1) & 1);

        const uint32_t tbase = sb + (s & 1) * STAGE_SZ;
#pragma unroll
        for (int kk = 0; kk < 4; kk++) {
            const uint32_t aoff = (uint32_t)(arow * 128
                                  + (((2 * kk + kblk) ^ axor) & 7) * 16);
            uint32_t a0[4], a1[4];
            ldsm4(a0, tbase + X0_OFF + aoff);
            ldsm4(a1, tbase + X1_OFF + aoff);
#pragma unroll
            for (int p = 0; p < 2; p++) {
                const uint32_t boff = swz((uint32_t)((half * 32 + p * 16 + t8 + rsel) * 128
                                                     + kk * 32 + bsel));
                uint32_t b0[4], b1[4];
                ldsm4(b0, tbase + W_OFF + boff);
                ldsm4(b1, tbase + W_OFF + 8192 + boff);

                mma16816(acc0[2 * p],     a0, b0[0], b0[2]);
                mma16816(acc0[2 * p + 1], a0, b0[1], b0[3]);
                mma16816(acc1[2 * p],     a1, b0[0], b0[2]);
                mma16816(acc1[2 * p + 1], a1, b0[1], b0[3]);
                mma16816(acc1[2 * p],     a0, b1[0], b1[2]);
                mma16816(acc1[2 * p + 1], a0, b1[1], b1[3]);
            }
        }
        __syncthreads();
    }

    // ---- epilogue: combine -> smem -> coalesced partial write ----
    float* Ls = (float*)smem;     // [64][65]
#pragma unroll
    for (int t = 0; t < 2; t++) {
        int tok = slab * 16 + (lane >> 2) + t * 8;
#pragma unroll
        for (int nt = 0; nt < 4; nt++) {
            int e0 = half * 32 + nt * 8 + (lane & 3) * 2;
            Ls[tok * LROW + e0 + 0] = acc0[nt][t * 2 + 0] + acc1[nt][t * 2 + 0] * INV2048;
            Ls[tok * LROW + e0 + 1] = acc0[nt][t * 2 + 1] + acc1[nt][t * 2 + 1] * INV2048;
        }
    }
    __syncthreads();

    float* gp = g_part + ((size_t)kh * NTOK + m0) * NEXP;
#pragma unroll
    for (int k = 0; k < 4; k++) {
        int f = tid + k * THREADS;          // float4 index in [0,1024)
        int token = f >> 4, c4 = f & 15;
        float4 v;
        v.x = Ls[token * LROW + c4 * 4 + 0];
        v.y = Ls[token * LROW + c4 * 4 + 1];
        v.z = Ls[token * LROW + c4 * 4 + 2];
        v.w = Ls[token * LROW + c4 * 4 + 3];
        *(float4*)(gp + token * NEXP + c4 * 4) = v;
    }
}

// ---------- reduce: sum halves, top-2 + softmax ----------
__global__ void __launch_bounds__(THREADS)
reduce_topk(float* __restrict__ out, int out_size) {
    __shared__ float Ls[MTILE * LROW];
    const int tid = threadIdx.x;
    const int m0  = blockIdx.x * MTILE;

    const float4* p0 = (const float4*)(g_part + (size_t)m0 * NEXP);
    const float4* p1 = (const float4*)(g_part + (size_t)NTOK * NEXP + (size_t)m0 * NEXP);
#pragma unroll
    for (int k = 0; k < 4; k++) {
        int f = tid + k * THREADS;
        int token = f >> 4, c4 = f & 15;
        float4 a = p0[f];
        float4 b = p1[f];
        Ls[token * LROW + c4 * 4 + 0] = a.x + b.x;
        Ls[token * LROW + c4 * 4 + 1] = a.y + b.y;
        Ls[token * LROW + c4 * 4 + 2] = a.z + b.z;
        Ls[token * LROW + c4 * 4 + 3] = a.w + b.w;
    }
    __syncthreads();

    if (tid < MTILE) {
        const float* row = Ls + tid * LROW;
        float v1 = -INFINITY, v2 = -INFINITY;
        int i1 = 0, i2 = 0;
#pragma unroll 8
        for (int e = 0; e < NEXP; e++) {
            float v = row[e];
            if (v > v1)      { v2 = v1; i2 = i1; v1 = v; i1 = e; }
            else if (v > v2) { v2 = v;  i2 = e; }
        }
        float e2  = __expf(v2 - v1);
        float inv = 1.0f / (1.0f + e2);
        const int g = m0 + tid;
        out[g * 2 + 0] = inv;
        out[g * 2 + 1] = e2 * inv;
        const int sc = NTOK * 2;
        if (out_size >= 2 * sc) {
            out[sc + g * 2 + 0] = (float)i1;
            out[sc + g * 2 + 1] = (float)i2;
        }
    }
}

extern "C" void kernel_launch(void* const* d_in, const int* in_sizes, int n_in,
                              void* d_out, int out_size) {
    const float* X = (const float*)d_in[0];
    const float* W = (const float*)d_in[1];
    float* out = (float*)d_out;

    cudaFuncSetAttribute(router_main, cudaFuncAttributeMaxDynamicSharedMemorySize,
                         SMEM_TOTAL);
    prep_w<<<(NCH_ALL * NEXP * 8) / THREADS, THREADS>>>(W);   // 128 CTAs
    router_main<<<dim3(NTOK / MTILE, KSPLIT), THREADS, SMEM_TOTAL>>>(X);
    reduce_topk<<<NTOK / MTILE, THREADS>>>(out, out_size);
}

// round 13
// speedup vs baseline: 1.1293x; 1.1293x over previous
#include <cuda_runtime.h>
#include <cuda_fp16.h>
#include <cstdint>
#include <math.h>

// TopK router: logits = X[16384,4096] @ W[64,4096]^T, top-2 + softmax.
// 3-term 2-level fp16 split on mma.sync.m16n8k16 (fp32 accum), split-K=4
// (1024 tasks for per-SM work balance; mma.sync issue-rate is the binding
// pipe at ~512 MAC/cyc/SM).
// W: pre-split/pre-swizzled/stage-blocked (prep_w); one cp.async.bulk/stage.
// X: LDG.128 -> in-register fp16 split -> STS.128, XOR-unit swizzle.

#define DIM     4096
#define NEXP    64
#define MTILE   64
#define KC      64
#define KSPLIT  4
#define KHALF   (DIM / KSPLIT)      // 1024
#define NCH_H   (KHALF / KC)        // 16 stages per CTA
#define NCH_ALL (DIM / KC)          // 64 global stages
#define NTOK    16384
#define THREADS 256
#define INV2048 4.8828125e-4f

#define X0_OFF  0                   // 8KB  (64 rows x 128B)
#define X1_OFF  8192                // 8KB
#define W_OFF   16384               // 16KB (w0 8KB | w1 8KB)
#define STAGE_SZ 32768
#define MB_OFF  65536
#define SMEM_TOTAL (2 * STAGE_SZ + 64)
#define LROW 65

__device__ __align__(16) uint8_t g_wst[NCH_ALL * 16384];   // 1MB staged W
__device__ float g_part[KSPLIT * NTOK * NEXP];             // 16MB partials

// ---------- helpers ----------
__device__ __forceinline__ uint32_t smem_u32(const void* p) {
    uint32_t a;
    asm("{ .reg .u64 t; cvta.to.shared.u64 t, %1; cvt.u32.u64 %0, t; }" : "=r"(a) : "l"(p));
    return a;
}
__device__ __forceinline__ uint32_t swz(uint32_t o) { return o ^ ((o >> 3) & 0x70); }

__device__ __forceinline__ uint32_t pack_f16(float hi, float lo) {
    uint32_t r;
    asm("cvt.rn.f16x2.f32 %0, %1, %2;" : "=r"(r) : "f"(hi), "f"(lo));
    return r;
}
__device__ __forceinline__ float2 unpack_f16(uint32_t u) {
    __half2 h = *reinterpret_cast<__half2*>(&u);
    return __half22float2(h);
}
__device__ __forceinline__ void sts128(uint32_t a, uint32_t x, uint32_t y,
                                       uint32_t z, uint32_t w) {
    asm volatile("st.shared.v4.b32 [%0], {%1, %2, %3, %4};"
                 :: "r"(a), "r"(x), "r"(y), "r"(z), "r"(w) : "memory");
}
__device__ __forceinline__ void ldsm4(uint32_t r[4], uint32_t addr) {
    asm volatile("ldmatrix.sync.aligned.m8n8.x4.shared.b16 {%0,%1,%2,%3}, [%4];"
                 : "=r"(r[0]), "=r"(r[1]), "=r"(r[2]), "=r"(r[3]) : "r"(addr));
}
__device__ __forceinline__ void mma16816(float d[4], const uint32_t a[4],
                                         uint32_t b0, uint32_t b1) {
    asm volatile("mma.sync.aligned.m16n8k16.row.col.f32.f16.f16.f32 "
                 "{%0,%1,%2,%3}, {%4,%5,%6,%7}, {%8,%9}, {%0,%1,%2,%3};"
                 : "+f"(d[0]), "+f"(d[1]), "+f"(d[2]), "+f"(d[3])
                 : "r"(a[0]), "r"(a[1]), "r"(a[2]), "r"(a[3]), "r"(b0), "r"(b1));
}

#define MBARRIER_INIT(addr, cnt) \
    asm volatile("mbarrier.init.shared.b64 [%0], %1;" \
                 :: "r"((uint32_t)(addr)), "r"((uint32_t)(cnt)) : "memory")
#define MBARRIER_EXPECT_TX(addr, tx) \
    asm volatile("mbarrier.arrive.expect_tx.shared.b64 _, [%0], %1;" \
                 :: "r"((uint32_t)(addr)), "r"((uint32_t)(tx)) : "memory")
#define MBARRIER_WAIT_PARITY(mbar_smem_addr, phase_parity) do { \
    uint32_t _mbar = (uint32_t)(mbar_smem_addr); \
    uint32_t _parity = (uint32_t)(phase_parity); \
    uint32_t _done; \
    asm volatile("{\n\t.reg .pred p;\n\t" \
        "mbarrier.try_wait.parity.acquire.cta.shared::cta.b64 p, [%1], %2;\n\t" \
        "selp.b32 %0, 1, 0, p;\n\t}" \
        : "=r"(_done) : "r"(_mbar), "r"(_parity) : "memory"); \
    if (!_done) { \
        asm volatile("{\n\t.reg .pred P1;\n\t" \
            "WAIT_LOOP_%=:\n\t" \
            "mbarrier.try_wait.parity.acquire.cta.shared::cta.b64 P1, [%0], %1, 0x989680;\n\t" \
            "@P1 bra.uni WAIT_DONE_%=;\n\t" \
            "bra.uni WAIT_LOOP_%=;\n\t" \
            "WAIT_DONE_%=:\n\t}" \
            :: "r"(_mbar), "r"(_parity) : "memory"); \
    } \
} while (0)

__device__ __forceinline__ void bulk_g2s(uint32_t dst, const void* src,
                                         uint32_t bytes, uint32_t mbar) {
    asm volatile(
        "cp.async.bulk.shared::cta.global.mbarrier::complete_tx::bytes "
        "[%0], [%1], %2, [%3];"
        :: "r"(dst), "l"(src), "r"(bytes), "r"(mbar) : "memory");
}

// ---------- W prep: split + swizzle + stage-block ----------
__global__ void prep_w(const float* __restrict__ W) {
    const int uid = blockIdx.x * blockDim.x + threadIdx.x;  // 0..32767
    const int gs = uid >> 9;          // global stage 0..63
    const int r  = (uid >> 3) & 63;   // expert row
    const int c  = uid & 7;           // 8-k unit
    const float* src = W + (size_t)r * DIM + gs * KC + c * 8;
    float4 v0 = *(const float4*)src;
    float4 v1 = *(const float4*)(src + 4);

    uint32_t h0 = pack_f16(v0.y, v0.x), h1 = pack_f16(v0.w, v0.z);
    uint32_t h2 = pack_f16(v1.y, v1.x), h3 = pack_f16(v1.w, v1.z);
    float2 u0 = unpack_f16(h0), u1 = unpack_f16(h1);
    float2 u2 = unpack_f16(h2), u3 = unpack_f16(h3);
    uint32_t l0 = pack_f16((v0.y - u0.y) * 2048.0f, (v0.x - u0.x) * 2048.0f);
    uint32_t l1 = pack_f16((v0.w - u1.y) * 2048.0f, (v0.z - u1.x) * 2048.0f);
    uint32_t l2 = pack_f16((v1.y - u2.y) * 2048.0f, (v1.x - u2.x) * 2048.0f);
    uint32_t l3 = pack_f16((v1.w - u3.y) * 2048.0f, (v1.z - u3.x) * 2048.0f);

    uint8_t* base = g_wst + (size_t)gs * 16384;
    const uint32_t off = swz((uint32_t)(r * 128 + c * 16));
    *(uint4*)(base + off)        = make_uint4(h0, h1, h2, h3);
    *(uint4*)(base + 8192 + off) = make_uint4(l0, l1, l2, l3);
}

// ---------- X staging ----------
__device__ __forceinline__ void load_x(const float* __restrict__ xg0,
                                       const float* __restrict__ xg1,
                                       int s, float4 x[4]) {
    x[0] = *(const float4*)(xg0 + s * KC);
    x[1] = *(const float4*)(xg0 + s * KC + 4);
    x[2] = *(const float4*)(xg1 + s * KC);
    x[3] = *(const float4*)(xg1 + s * KC + 4);
}

__device__ __forceinline__ void store_x_unit(uint32_t tbase, int row, int k8,
                                             float4 v0, float4 v1) {
    uint32_t h0 = pack_f16(v0.y, v0.x), h1 = pack_f16(v0.w, v0.z);
    uint32_t h2 = pack_f16(v1.y, v1.x), h3 = pack_f16(v1.w, v1.z);
    float2 u0 = unpack_f16(h0), u1 = unpack_f16(h1);
    float2 u2 = unpack_f16(h2), u3 = unpack_f16(h3);
    uint32_t l0 = pack_f16((v0.y - u0.y) * 2048.0f, (v0.x - u0.x) * 2048.0f);
    uint32_t l1 = pack_f16((v0.w - u1.y) * 2048.0f, (v0.z - u1.x) * 2048.0f);
    uint32_t l2 = pack_f16((v1.y - u2.y) * 2048.0f, (v1.x - u2.x) * 2048.0f);
    uint32_t l3 = pack_f16((v1.w - u3.y) * 2048.0f, (v1.z - u3.x) * 2048.0f);
    const uint32_t off = (uint32_t)(row * 128 + (((k8) ^ (row & 7)) & 7) * 16);
    sts128(tbase + X0_OFF + off, h0, h1, h2, h3);
    sts128(tbase + X1_OFF + off, l0, l1, l2, l3);
}

// ---------- main kernel (partial GEMM over one K-quarter) ----------
__global__ void __launch_bounds__(THREADS, 3)
router_main(const float* __restrict__ X) {
    extern __shared__ __align__(1024) char smem[];
    const uint32_t sb = smem_u32(smem);
    const int tid  = threadIdx.x;
    const int lane = tid & 31;
    const int wid  = tid >> 5;
    const int m0   = blockIdx.x * MTILE;
    const int kh   = blockIdx.y;
    const int kbase = kh * KHALF;
    const int gs0   = kh * NCH_H;     // first global W stage

    const int xrow = tid >> 3;        // 0..31
    const int xk8  = tid & 7;
    const float* xg0 = X + (size_t)(m0 + xrow) * DIM + kbase + xk8 * 8;
    const float* xg1 = xg0 + (size_t)32 * DIM;

    const int slab = wid & 3;
    const int half = wid >> 2;
    const int t8   = lane & 7;
    const int mat  = lane >> 3;
    const int rsel = (mat & 1) * 8;
    const int kblk = mat >> 1;
    const int bsel = kblk * 16;
    const int arow = slab * 16 + t8 + rsel;
    const int axor = arow & 7;
    const int brow0 = (half * 32 + t8 + rsel) * 128;

    const uint32_t mb0 = sb + MB_OFF;
    const uint32_t mb1 = sb + MB_OFF + 8;

    float acc0[4][4], acc1[4][4];
#pragma unroll
    for (int n = 0; n < 4; n++)
#pragma unroll
        for (int j = 0; j < 4; j++) { acc0[n][j] = 0.0f; acc1[n][j] = 0.0f; }

    if (tid == 0) { MBARRIER_INIT(mb0, 1); MBARRIER_INIT(mb1, 1); }
    __syncthreads();

    // prologue
    float4 xr[4];
    if (tid == 0) {
        MBARRIER_EXPECT_TX(mb0, 16384);
        bulk_g2s(sb + W_OFF, g_wst + (size_t)gs0 * 16384, 16384, mb0);
    }
    load_x(xg0, xg1, 0, xr);
    store_x_unit(sb, xrow, xk8, xr[0], xr[1]);
    store_x_unit(sb, xrow + 32, xk8, xr[2], xr[3]);
    load_x(xg0, xg1, 1, xr);
    __syncthreads();

    for (int s = 0; s < NCH_H; s++) {
        if (s + 1 < NCH_H) {
            const uint32_t nb = sb + ((s + 1) & 1) * STAGE_SZ;
            store_x_unit(nb, xrow, xk8, xr[0], xr[1]);
            store_x_unit(nb, xrow + 32, xk8, xr[2], xr[3]);
            if (tid == 0) {
                const uint32_t mbn = ((s + 1) & 1) ? mb1 : mb0;
                MBARRIER_EXPECT_TX(mbn, 16384);
                bulk_g2s(nb + W_OFF, g_wst + (size_t)(gs0 + s + 1) * 16384,
                         16384, mbn);
            }
        }
        if (s + 2 < NCH_H)
            load_x(xg0, xg1, s + 2, xr);

        MBARRIER_WAIT_PARITY((s & 1) ? mb1 : mb0, (s >> 1) & 1);

        const uint32_t tbase = sb + (s & 1) * STAGE_SZ;
#pragma unroll
        for (int kk = 0; kk < 4; kk++) {
            const uint32_t aoff = (uint32_t)(arow * 128
                                  + (((2 * kk + kblk) ^ axor) & 7) * 16);
            const uint32_t boff0 = swz((uint32_t)(brow0 + kk * 32 + bsel));
            const uint32_t boff1 = swz((uint32_t)(brow0 + 16 * 128 + kk * 32 + bsel));

            uint32_t a0[4], a1[4], b0a[4], b0b[4];
            ldsm4(a0, tbase + X0_OFF + aoff);
            ldsm4(a1, tbase + X1_OFF + aoff);
            ldsm4(b0a, tbase + W_OFF + boff0);
            ldsm4(b0b, tbase + W_OFF + boff1);

            // 8 back-to-back HMMA on w0
            mma16816(acc0[0], a0, b0a[0], b0a[2]);
            mma16816(acc0[1], a0, b0a[1], b0a[3]);
            mma16816(acc0[2], a0, b0b[0], b0b[2]);
            mma16816(acc0[3], a0, b0b[1], b0b[3]);
            mma16816(acc1[0], a1, b0a[0], b0a[2]);
            mma16816(acc1[1], a1, b0a[1], b0a[3]);
            mma16816(acc1[2], a1, b0b[0], b0b[2]);
            mma16816(acc1[3], a1, b0b[1], b0b[3]);

            uint32_t b1a[4], b1b[4];
            ldsm4(b1a, tbase + W_OFF + 8192 + boff0);
            ldsm4(b1b, tbase + W_OFF + 8192 + boff1);

            // 4 HMMA on w1
            mma16816(acc1[0], a0, b1a[0], b1a[2]);
            mma16816(acc1[1], a0, b1a[1], b1a[3]);
            mma16816(acc1[2], a0, b1b[0], b1b[2]);
            mma16816(acc1[3], a0, b1b[1], b1b[3]);
        }
        __syncthreads();
    }

    // ---- epilogue: combine -> smem -> coalesced partial write ----
    float* Ls = (float*)smem;     // [64][65]
#pragma unroll
    for (int t = 0; t < 2; t++) {
        int tok = slab * 16 + (lane >> 2) + t * 8;
#pragma unroll
        for (int nt = 0; nt < 4; nt++) {
            int e0 = half * 32 + nt * 8 + (lane & 3) * 2;
            Ls[tok * LROW + e0 + 0] = acc0[nt][t * 2 + 0] + acc1[nt][t * 2 + 0] * INV2048;
            Ls[tok * LROW + e0 + 1] = acc0[nt][t * 2 + 1] + acc1[nt][t * 2 + 1] * INV2048;
        }
    }
    __syncthreads();

    float* gp = g_part + ((size_t)kh * NTOK + m0) * NEXP;
#pragma unroll
    for (int k = 0; k < 4; k++) {
        int f = tid + k * THREADS;          // float4 index in [0,1024)
        int token = f >> 4, c4 = f & 15;
        float4 v;
        v.x = Ls[token * LROW + c4 * 4 + 0];
        v.y = Ls[token * LROW + c4 * 4 + 1];
        v.z = Ls[token * LROW + c4 * 4 + 2];
        v.w = Ls[token * LROW + c4 * 4 + 3];
        *(float4*)(gp + token * NEXP + c4 * 4) = v;
    }
}

// ---------- reduce: sum 4 partials, top-2 + softmax ----------
__global__ void __launch_bounds__(THREADS)
reduce_topk(float* __restrict__ out, int out_size) {
    __shared__ float Ls[MTILE * LROW];
    const int tid = threadIdx.x;
    const int m0  = blockIdx.x * MTILE;

#pragma unroll
    for (int k = 0; k < 4; k++) {
        int f = tid + k * THREADS;
        int token = f >> 4, c4 = f & 15;
        float4 s = ((const float4*)(g_part + (size_t)m0 * NEXP))[f];
#pragma unroll
        for (int kh = 1; kh < KSPLIT; kh++) {
            float4 b = ((const float4*)(g_part + ((size_t)kh * NTOK + m0) * NEXP))[f];
            s.x += b.x; s.y += b.y; s.z += b.z; s.w += b.w;
        }
        Ls[token * LROW + c4 * 4 + 0] = s.x;
        Ls[token * LROW + c4 * 4 + 1] = s.y;
        Ls[token * LROW + c4 * 4 + 2] = s.z;
        Ls[token * LROW + c4 * 4 + 3] = s.w;
    }
    __syncthreads();

    if (tid < MTILE) {
        const float* row = Ls + tid * LROW;
        float v1 = -INFINITY, v2 = -INFINITY;
        int i1 = 0, i2 = 0;
#pragma unroll 8
        for (int e = 0; e < NEXP; e++) {
            float v = row[e];
            if (v > v1)      { v2 = v1; i2 = i1; v1 = v; i1 = e; }
            else if (v > v2) { v2 = v;  i2 = e; }
        }
        float e2  = __expf(v2 - v1);
        float inv = 1.0f / (1.0f + e2);
        const int g = m0 + tid;
        out[g * 2 + 0] = inv;
        out[g * 2 + 1] = e2 * inv;
        const int sc = NTOK * 2;
        if (out_size >= 2 * sc) {
            out[sc + g * 2 + 0] = (float)i1;
            out[sc + g * 2 + 1] = (float)i2;
        }
    }
}

extern "C" void kernel_launch(void* const* d_in, const int* in_sizes, int n_in,
                              void* d_out, int out_size) {
    const float* X = (const float*)d_in[0];
    const float* W = (const float*)d_in[1];
    float* out = (float*)d_out;

    cudaFuncSetAttribute(router_main, cudaFuncAttributeMaxDynamicSharedMemorySize,
                         SMEM_TOTAL);
    prep_w<<<(NCH_ALL * NEXP * 8) / THREADS, THREADS>>>(W);
    router_main<<<dim3(NTOK / MTILE, KSPLIT), THREADS, SMEM_TOTAL>>>(X);
    reduce_topk<<<NTOK / MTILE, THREADS>>>(out, out_size);
}